// round 16
// baseline (speedup 1.0000x reference)
#include <cuda_runtime.h>
#include <cuda_fp16.h>
#include <cstdint>

// ---------------------------------------------------------------------------
// Problem constants
// ---------------------------------------------------------------------------
#define NEURONS  512
#define CHANNELS 384
#define HWSZ     169
#define BATCH    512
#define K_TOTAL  (CHANNELS * HWSZ)      // 64896

// GEMM: CTA 128x128, 4 warps of 64x64. A fp32 direct from x in k32 tiles
// (4 stages); B fp16 from g_w (pi-permuted) in k64 tiles (3 stages).
#define BM 128
#define BN 128
#define SPLITS 18                        // 6 splits of 57 k64-tiles + 12 of 56

#define A_STAGE  (BM * 128)              // k32 fp32 tile: 16 KB (one swizzle panel)
#define A_STAGES 4
#define B_STAGE  (BN * 128)              // k64 fp16 tile: 16 KB
#define B_STAGES 3
#define A_TOTAL  (A_STAGES * A_STAGE)    // 64 KB
#define SMEM_TOTAL (A_TOTAL + B_STAGES * B_STAGE)   // 112 KB

// prep grid: build g_w (pi-permuted) | init out with bias
#define W_BLOCKS    (NEURONS * 4)                             // 2048
#define OUT_BLOCKS  ((BATCH * NEURONS) / (256 * 4))           // 256
#define PREP_BLOCKS (W_BLOCKS + OUT_BLOCKS)                   // 2304

// Scratch (__device__ globals per allocation rules)
__device__ __half g_w[(size_t)NEURONS * K_TOTAL];    // fp16, pi-permuted per k16

// ---------------------------------------------------------------------------
// Helpers (baseline PTX: sm_80-class; compute_103 target has no 'a' isa)
// ---------------------------------------------------------------------------
__device__ __forceinline__ uint32_t s2u(const void* p) {
    return (uint32_t)__cvta_generic_to_shared(p);
}

// Full SW128 swizzle within a 128-row x 128B panel: conflict-free for
// cp.async row fills and ldmatrix 8x8 column reads.
__device__ __forceinline__ uint32_t sw_off(uint32_t row, uint32_t c16) {
    return row * 128u + ((c16 ^ (row & 7u)) << 4);
}

// pack two fp32 into one f16x2 reg: {hi, lo}
__device__ __forceinline__ uint32_t pack_f16(float hi, float lo) {
    uint32_t d;
    asm("cvt.rn.f16x2.f32 %0, %1, %2;" : "=r"(d) : "f"(hi), "f"(lo));
    return d;
}

#define CPA16(dst, src) \
    asm volatile("cp.async.cg.shared.global [%0], [%1], 16;" :: "r"(dst), "l"(src))
#define CP_COMMIT()  asm volatile("cp.async.commit_group;" ::: "memory")
#define CP_WAIT(n)   asm volatile("cp.async.wait_group %0;" :: "n"(n) : "memory")

#define LDSM_X4(r0, r1, r2, r3, a) \
    asm volatile("ldmatrix.sync.aligned.m8n8.x4.shared.b16 {%0,%1,%2,%3}, [%4];" \
                 : "=r"(r0), "=r"(r1), "=r"(r2), "=r"(r3) : "r"(a))

// fp16 MMA: m16n8k16, f32 accum
#define MMA_F16(c, a, b) \
    asm volatile("mma.sync.aligned.m16n8k16.row.col.f32.f16.f16.f32 " \
                 "{%0,%1,%2,%3},{%4,%5,%6,%7},{%8,%9},{%0,%1,%2,%3};" \
                 : "+f"((c)[0]), "+f"((c)[1]), "+f"((c)[2]), "+f"((c)[3]) \
                 : "r"((a)[0]), "r"((a)[1]), "r"((a)[2]), "r"((a)[3]), \
                   "r"((b)[0]), "r"((b)[1]))

// fire-and-forget global fp32 reduction (REDG, sm_60+ baseline)
#define REDADD(p, v) \
    asm volatile("red.global.add.f32 [%0], %1;" :: "l"(p), "f"(v) : "memory")

// ---------------------------------------------------------------------------
// Kernel 1: prep (unchanged from R15).
//   [0, W_BLOCKS): g_w = fp16(W_d*W_s), pi-permuted within each k16 group:
//     stored = {r0,r4,r1,r5,r2,r6,r3,r7, r8,r12,r9,r13,r10,r14,r11,r15}
//   [W_BLOCKS, ..): out[b,n] = W_b[n].
// ---------------------------------------------------------------------------
__global__ void __launch_bounds__(256) prep(const float* __restrict__ W_s,
                                            const float* __restrict__ W_d,
                                            const float* __restrict__ W_b,
                                            float* __restrict__ out) {
    if (blockIdx.x < W_BLOCKS) {
        const int n = blockIdx.x >> 2;
        const int q = blockIdx.x & 3;
        __shared__ float ws[HWSZ];
        __shared__ float wd[CHANNELS];
        for (int i = threadIdx.x; i < HWSZ; i += 256)     ws[i] = W_s[n * HWSZ + i];
        for (int i = threadIdx.x; i < CHANNELS; i += 256) wd[i] = W_d[n * CHANNELS + i];
        __syncthreads();
        const int QK = K_TOTAL / 4;                      // 16224
        const int kbase = q * QK;
        uint4* dst = (uint4*)(g_w + (size_t)n * K_TOTAL + kbase);
        for (int v = threadIdx.x; v < QK / 16; v += 256) {   // k16-groups
            int k = kbase + v * 16;
            float r[16];
            #pragma unroll
            for (int i = 0; i < 16; i++) {
                int ki = k + i;
                int c  = ki / HWSZ;                      // constant divisor -> mul-hi
                int hw = ki - c * HWSZ;
                r[i] = wd[c] * ws[hw];
            }
            uint4 o0, o1;
            o0.x = pack_f16(r[4],  r[0]);
            o0.y = pack_f16(r[5],  r[1]);
            o0.z = pack_f16(r[6],  r[2]);
            o0.w = pack_f16(r[7],  r[3]);
            o1.x = pack_f16(r[12], r[8]);
            o1.y = pack_f16(r[13], r[9]);
            o1.z = pack_f16(r[14], r[10]);
            o1.w = pack_f16(r[15], r[11]);
            dst[v * 2]     = o0;
            dst[v * 2 + 1] = o1;
        }
    } else {
        const int i4 = (blockIdx.x - W_BLOCKS) * 256 + threadIdx.x;
        const int n4 = i4 & (NEURONS / 4 - 1);
        ((float4*)out)[i4] = ((const float4*)W_b)[n4];
    }
}

// ---------------------------------------------------------------------------
// Kernel 2: fp16 mma.sync split-K GEMM, A fp32 from x (k32 tiles, 4 stages),
// B fp16 (k64 tiles, 3 stages, committed with even A fills). 128 threads.
// ---------------------------------------------------------------------------
__global__ void __launch_bounds__(128, 2) gemm_f16(const float* __restrict__ x,
                                                   float* __restrict__ out) {
    extern __shared__ char smem[];
    const uint32_t sbase = s2u(smem);

    const int tid  = threadIdx.x;
    const int wid  = tid >> 5;
    const int lane = tid & 31;
    const int n0 = blockIdx.x * BN;
    const int m0 = blockIdx.y * BM;
    const int s  = blockIdx.z;

    // uneven split-K over 1014 k64-tiles: first 6 splits get 57, rest 56
    const int NT  = 56 + (s < 6 ? 1 : 0);
    const int ts0 = 56 * s + (s < 6 ? s : 6);
    const int NT2 = NT * 2;                       // k32 tiles

    const float*  xbase = x   + (size_t)m0 * K_TOTAL + (size_t)ts0 * 64;
    const __half* wbase = g_w + (size_t)n0 * K_TOTAL + (size_t)ts0 * 64;

    const int wm = (wid & 1) * 64;        // warp m offset
    const int wn = (wid >> 1) * 64;       // warp n offset
    const int sub = lane >> 3;            // 0..3
    const int r8  = lane & 7;

    float acc[4][8][4];                   // 4 m16 x 8 n8 fragments
    #pragma unroll
    for (int i = 0; i < 4; i++)
        #pragma unroll
        for (int j = 0; j < 8; j++)
            #pragma unroll
            for (int f = 0; f < 4; f++) acc[i][j][f] = 0.f;

    // fill k32 A tile t (+ B k64 pair t/2 on even t); one commit group
    auto fill = [&](int t) {
        const uint32_t sa = sbase + (t & 3) * A_STAGE;
        const float* xs = xbase + (size_t)t * 32;
        #pragma unroll
        for (int i = 0; i < 8; i++) {            // A: 8 chunks/thread
            int slot = tid + i * 128;             // 0..1023
            uint32_t row = slot >> 3, c = slot & 7;
            CPA16(sa + sw_off(row, c), xs + (size_t)row * K_TOTAL + c * 4);
        }
        if (!(t & 1)) {
            const int j = t >> 1;
            const uint32_t sB = sbase + A_TOTAL + (j % 3) * B_STAGE;
            const __half* wr = wbase + (size_t)j * 64;
            #pragma unroll
            for (int i = 0; i < 8; i++) {        // B: 8 chunks/thread
                int slot = tid + i * 128;
                uint32_t row = slot >> 3, c = slot & 7;
                CPA16(sB + sw_off(row, c), wr + (size_t)row * K_TOTAL + c * 8);
            }
        }
        CP_COMMIT();
    };

    fill(0);
    fill(1);
    fill(2);

    for (int t = 0; t < NT2; t++) {
        // groups outstanding before wait: t .. min(t+2, NT2-1)
        if (t + 2 < NT2)      { CP_WAIT(2); }
        else if (t + 1 < NT2) { CP_WAIT(1); }
        else                  { CP_WAIT(0); }
        __syncthreads();
        if (t + 3 < NT2) fill(t + 3);    // stage (t+3)&3 == (t-1)&3: freed

        const uint32_t sa = sbase + (t & 3) * A_STAGE;
        const uint32_t sB = sbase + A_TOTAL + ((t >> 1) % 3) * B_STAGE;
        const uint32_t hb = (t & 1) * 4;          // k32 half within B k64 tile

        #pragma unroll
        for (int ks = 0; ks < 2; ks++) {          // two k16 steps per k32 tile
            // A: 4 m16k16 fragments from fp32 smem; 2 LDSM.x4 + 4 packs each
            uint32_t a[4][4];
            #pragma unroll
            for (int i = 0; i < 4; i++) {
                uint32_t row = wm + i * 16 + (sub & 1) * 8 + r8;
                uint32_t q0  = ks * 4 + (sub >> 1);
                uint32_t x0, x1, x2, x3, y0, y1, y2, y3;
                LDSM_X4(x0, x1, x2, x3, sa + sw_off(row, q0));
                LDSM_X4(y0, y1, y2, y3, sa + sw_off(row, q0 + 2));
                a[i][0] = pack_f16(__uint_as_float(x2), __uint_as_float(x0));
                a[i][1] = pack_f16(__uint_as_float(x3), __uint_as_float(x1));
                a[i][2] = pack_f16(__uint_as_float(y2), __uint_as_float(y0));
                a[i][3] = pack_f16(__uint_as_float(y3), __uint_as_float(y1));
            }
            // B: 8 n8k16 fragments via 4 LDSM.x4 (storage pi-permuted)
            uint32_t b[8][2];
            #pragma unroll
            for (int p = 0; p < 4; p++) {
                uint32_t row   = wn + p * 16 + (sub >> 1) * 8 + r8;
                uint32_t chunk = hb + ks * 2 + (sub & 1);
                uint32_t t0, t1, t2, t3;
                LDSM_X4(t0, t1, t2, t3, sB + sw_off(row, chunk));
                b[p * 2 + 0][0] = t0;  b[p * 2 + 0][1] = t1;
                b[p * 2 + 1][0] = t2;  b[p * 2 + 1][1] = t3;
            }
            #pragma unroll
            for (int i = 0; i < 4; i++)
                #pragma unroll
                for (int j = 0; j < 8; j++)
                    MMA_F16(acc[i][j], a[i], b[j]);
        }
        __syncthreads();
    }

    // epilogue: atomically accumulate the 64x64 warp tile into out
    const int g  = lane >> 2;
    const int t4 = lane & 3;
    #pragma unroll
    for (int i = 0; i < 4; i++) {
        #pragma unroll
        for (int j = 0; j < 8; j++) {
            int row = m0 + wm + i * 16 + g;
            int col = n0 + wn + j * 8 + t4 * 2;
            float* p0 = out + (size_t)row * NEURONS + col;
            float* p1 = out + (size_t)(row + 8) * NEURONS + col;
            REDADD(p0,     acc[i][j][0]);
            REDADD(p0 + 1, acc[i][j][1]);
            REDADD(p1,     acc[i][j][2]);
            REDADD(p1 + 1, acc[i][j][3]);
        }
    }
}

// ---------------------------------------------------------------------------
// Entry point
// ---------------------------------------------------------------------------
extern "C" void kernel_launch(void* const* d_in, const int* in_sizes, int n_in,
                              void* d_out, int out_size) {
    const float* x   = (const float*)d_in[0];   // [512, 384, 13, 13]
    const float* W_s = (const float*)d_in[1];   // [512, 13, 13]
    const float* W_d = (const float*)d_in[2];   // [512, 384]
    const float* W_b = (const float*)d_in[3];   // [1, 512]
    float* out = (float*)d_out;                 // [512, 512]

    (void)cudaFuncSetAttribute(gemm_f16,
        cudaFuncAttributeMaxDynamicSharedMemorySize, SMEM_TOTAL);

    prep<<<PREP_BLOCKS, 256>>>(W_s, W_d, W_b, out);

    dim3 grid(NEURONS / BN, BATCH / BM, SPLITS);   // 4 x 4 x 18 = 288 CTAs
    gemm_f16<<<grid, 128, SMEM_TOTAL>>>(x, out);
}